// round 3
// baseline (speedup 1.0000x reference)
#include <cuda_runtime.h>
#include <math.h>

// log(entmax_bisect_1.5(X)) row-wise. X: (rows, 32000) fp32, out same shape.
//
// p(z) = relu(z)^2 with z = 0.5*X - tau, tau s.t. sum p = 1. Dense support
// (guaranteed by input distribution) gives closed-form tau from S1, S2:
//   d*tau^2 - 2*S1*tau + (S2 - 1) = 0  =>  tau = (S1 - sqrt(S1^2 - d(S2-1)))/d
// validated by tau <= min(z). Fallback: exact 50-iter reference bisection
// re-reading the row from global (L2-resident).
//
// Pass 1 accumulates raw sums (no per-element scaling), pass 2 re-reads X
// from L2 and writes with streaming stores. 6 CTAs/SM for fine phase mixing.

constexpr int D  = 32000;
constexpr int D4 = D / 4;
constexpr int NT = 256;
constexpr int NW = NT / 32;

__device__ __forceinline__ float wsum(float v) {
#pragma unroll
    for (int o = 16; o; o >>= 1) v += __shfl_xor_sync(0xffffffffu, v, o);
    return v;
}
__device__ __forceinline__ float wmin(float v) {
#pragma unroll
    for (int o = 16; o; o >>= 1) v = fminf(v, __shfl_xor_sync(0xffffffffu, v, o));
    return v;
}
__device__ __forceinline__ float wmax(float v) {
#pragma unroll
    for (int o = 16; o; o >>= 1) v = fmaxf(v, __shfl_xor_sync(0xffffffffu, v, o));
    return v;
}

// Block-wide sum of relu(0.5*x[i] - tau)^2 over the row, broadcast.
// Fallback path only (support not dense) — row is L2-resident.
__device__ float block_relu2_sum(const float4* __restrict__ x4, float tau,
                                 float* redbuf, float* bc) {
    float acc = 0.f;
    for (int i = threadIdx.x; i < D4; i += NT) {
        float4 v = x4[i];
        float t;
        t = fmaxf(fmaf(0.5f, v.x, -tau), 0.f); acc = fmaf(t, t, acc);
        t = fmaxf(fmaf(0.5f, v.y, -tau), 0.f); acc = fmaf(t, t, acc);
        t = fmaxf(fmaf(0.5f, v.z, -tau), 0.f); acc = fmaf(t, t, acc);
        t = fmaxf(fmaf(0.5f, v.w, -tau), 0.f); acc = fmaf(t, t, acc);
    }
    acc = wsum(acc);
    int wid = threadIdx.x >> 5, lid = threadIdx.x & 31;
    __syncthreads();
    if (lid == 0) redbuf[wid] = acc;
    __syncthreads();
    if (threadIdx.x == 0) {
        float s = 0.f;
#pragma unroll
        for (int w = 0; w < NW; ++w) s += redbuf[w];
        *bc = s;
    }
    __syncthreads();
    return *bc;
}

__global__ void __launch_bounds__(NT, 6)
log_entmax_kernel(const float* __restrict__ X, float* __restrict__ Y) {
    __shared__ float redA[NW], redB[NW], redC[NW];
    __shared__ float s_tau, s_logsum, s_flag, s_bc;

    const int tid = threadIdx.x;
    const int wid = tid >> 5, lid = tid & 31;
    const float4* __restrict__ x4 = reinterpret_cast<const float4*>(X) + (size_t)blockIdx.x * D4;
    float4* __restrict__ y4       = reinterpret_cast<float4*>(Y)       + (size_t)blockIdx.x * D4;

    // ---- Pass 1: stream row from DRAM (fills L2), raw sums (no scaling) ----
    float s1 = 0.f, s2 = 0.f, mn = INFINITY;
#pragma unroll 4
    for (int i = tid; i < D4; i += NT) {
        float4 v = x4[i];
        s1 += (v.x + v.y) + (v.z + v.w);
        s2 = fmaf(v.x, v.x, s2); s2 = fmaf(v.y, v.y, s2);
        s2 = fmaf(v.z, v.z, s2); s2 = fmaf(v.w, v.w, s2);
        mn = fminf(mn, fminf(fminf(v.x, v.y), fminf(v.z, v.w)));
    }
    s1 = wsum(s1); s2 = wsum(s2); mn = wmin(mn);
    if (lid == 0) { redA[wid] = s1; redB[wid] = s2; redC[wid] = mn; }
    __syncthreads();

    if (tid == 0) {
        float S1 = 0.f, S2 = 0.f, MN = INFINITY;
#pragma unroll
        for (int w = 0; w < NW; ++w) {
            S1 += redA[w]; S2 += redB[w]; MN = fminf(MN, redC[w]);
        }
        S1 *= 0.5f;            // rescale raw sums to z = 0.5*x domain
        S2 *= 0.25f;
        MN *= 0.5f;
        const float k = (float)D;
        float disc  = fmaxf(fmaf(S1, S1, -k * (S2 - 1.0f)), 0.f);
        float tau   = (S1 - sqrtf(disc)) / k;
        float sum_p = fmaf(k * tau, tau, fmaf(-2.f * S1, tau, S2));
        s_tau = tau;
        if (tau <= MN && sum_p > 0.f) {           // dense support: closed form valid
            s_logsum = __logf(sum_p);
            s_flag = 1.f;
        } else {
            s_flag = 0.f;
        }
    }
    __syncthreads();

    // ---- Fallback: exact reference bisection (block-uniform branch) ----
    if (s_flag == 0.f) {
        // recompute block max (only needed here)
        float mx = -INFINITY;
        for (int i = tid; i < D4; i += NT) {
            float4 v = x4[i];
            mx = fmaxf(mx, fmaxf(fmaxf(v.x, v.y), fmaxf(v.z, v.w)));
        }
        mx = wmax(mx);
        __syncthreads();
        if (lid == 0) redA[wid] = mx;
        __syncthreads();
        if (tid == 0) {
            float M = -INFINITY;
#pragma unroll
            for (int w = 0; w < NW; ++w) M = fmaxf(M, redA[w]);
            s_bc = 0.5f * M;
        }
        __syncthreads();
        float mxv    = s_bc;
        float tau_lo = mxv - 1.0f;
        float tau_hi = mxv - sqrtf(1.0f / (float)D);
        float f_lo   = block_relu2_sum(x4, tau_lo, redA, &s_bc) - 1.0f;
        float dm     = tau_hi - tau_lo;
        float tau_m  = tau_lo;
        for (int it = 0; it < 50; ++it) {
            dm *= 0.5f;
            tau_m = tau_lo + dm;
            float f_m = block_relu2_sum(x4, tau_m, redA, &s_bc) - 1.0f;
            if (f_m * f_lo >= 0.f) tau_lo = tau_m;  // uniform across block
        }
        float sp = block_relu2_sum(x4, tau_m, redA, &s_bc);
        if (tid == 0) {
            s_tau = tau_m;
            s_logsum = __logf(sp);
        }
        __syncthreads();
    }

    const float tau    = s_tau;
    const float logsum = s_logsum;

    // ---- Pass 2: re-read X (L2 hit), write log p with streaming stores ----
#pragma unroll 4
    for (int i = tid; i < D4; i += NT) {
        float4 v = __ldcs(&x4[i]);   // evict-first: row is dead after this read
        float4 r;
        float t;
        t = fmaf(0.5f, v.x, -tau); r.x = (t > 0.f) ? fmaf(2.f, __logf(t), -logsum) : -INFINITY;
        t = fmaf(0.5f, v.y, -tau); r.y = (t > 0.f) ? fmaf(2.f, __logf(t), -logsum) : -INFINITY;
        t = fmaf(0.5f, v.z, -tau); r.z = (t > 0.f) ? fmaf(2.f, __logf(t), -logsum) : -INFINITY;
        t = fmaf(0.5f, v.w, -tau); r.w = (t > 0.f) ? fmaf(2.f, __logf(t), -logsum) : -INFINITY;
        __stcs(&y4[i], r);           // streaming store: don't pollute L2
    }
}

extern "C" void kernel_launch(void* const* d_in, const int* in_sizes, int n_in,
                              void* d_out, int out_size) {
    const float* X = (const float*)d_in[0];
    float* Y = (float*)d_out;
    const int rows = in_sizes[0] / D;
    log_entmax_kernel<<<rows, NT>>>(X, Y);
}

// round 4
// speedup vs baseline: 1.2464x; 1.2464x over previous
#include <cuda_runtime.h>
#include <math.h>

// log(entmax_bisect_1.5(X)) row-wise. X: (rows, 32000) fp32, out same shape.
//
// p(z) = relu(z)^2 with z = 0.5*X - tau, tau s.t. sum p = 1. Dense support
// (guaranteed by input distribution) gives closed-form tau from S1, S2:
//   d*tau^2 - 2*S1*tau + (S2 - 1) = 0  =>  tau = (S1 - sqrt(S1^2 - d(S2-1)))/d
// validated by tau <= min(z). Fallback: exact 50-iter reference bisection
// re-reading the row from global (L2-resident).
//
// NT=512 x 3 CTAs/SM: L2 row working set = 3*148*128KB = 55MB << 126MB L2,
// so pass-2 re-reads hit L2 (R3 showed 6 CTAs/SM = 113MB thrashes L2).
// Pass 1 accumulates raw sums (scale folded out), pass 2 streams output.

constexpr int D  = 32000;
constexpr int D4 = D / 4;
constexpr int NT = 512;
constexpr int NW = NT / 32;

__device__ __forceinline__ float wsum(float v) {
#pragma unroll
    for (int o = 16; o; o >>= 1) v += __shfl_xor_sync(0xffffffffu, v, o);
    return v;
}
__device__ __forceinline__ float wmin(float v) {
#pragma unroll
    for (int o = 16; o; o >>= 1) v = fminf(v, __shfl_xor_sync(0xffffffffu, v, o));
    return v;
}
__device__ __forceinline__ float wmax(float v) {
#pragma unroll
    for (int o = 16; o; o >>= 1) v = fmaxf(v, __shfl_xor_sync(0xffffffffu, v, o));
    return v;
}

// Block-wide sum of relu(0.5*x[i] - tau)^2 over the row, broadcast.
// Fallback path only (support not dense) — row is L2-resident.
__device__ float block_relu2_sum(const float4* __restrict__ x4, float tau,
                                 float* redbuf, float* bc) {
    float acc = 0.f;
    for (int i = threadIdx.x; i < D4; i += NT) {
        float4 v = x4[i];
        float t;
        t = fmaxf(fmaf(0.5f, v.x, -tau), 0.f); acc = fmaf(t, t, acc);
        t = fmaxf(fmaf(0.5f, v.y, -tau), 0.f); acc = fmaf(t, t, acc);
        t = fmaxf(fmaf(0.5f, v.z, -tau), 0.f); acc = fmaf(t, t, acc);
        t = fmaxf(fmaf(0.5f, v.w, -tau), 0.f); acc = fmaf(t, t, acc);
    }
    acc = wsum(acc);
    int wid = threadIdx.x >> 5, lid = threadIdx.x & 31;
    __syncthreads();
    if (lid == 0) redbuf[wid] = acc;
    __syncthreads();
    if (threadIdx.x == 0) {
        float s = 0.f;
#pragma unroll
        for (int w = 0; w < NW; ++w) s += redbuf[w];
        *bc = s;
    }
    __syncthreads();
    return *bc;
}

__global__ void __launch_bounds__(NT, 3)
log_entmax_kernel(const float* __restrict__ X, float* __restrict__ Y) {
    __shared__ float redA[NW], redB[NW], redC[NW];
    __shared__ float s_tau, s_logsum, s_flag, s_bc;

    const int tid = threadIdx.x;
    const int wid = tid >> 5, lid = tid & 31;
    const float4* __restrict__ x4 = reinterpret_cast<const float4*>(X) + (size_t)blockIdx.x * D4;
    float4* __restrict__ y4       = reinterpret_cast<float4*>(Y)       + (size_t)blockIdx.x * D4;

    // ---- Pass 1: stream row from DRAM (fills L2), raw sums (no scaling) ----
    float s1 = 0.f, s2 = 0.f, mn = INFINITY;
#pragma unroll 4
    for (int i = tid; i < D4; i += NT) {
        float4 v = x4[i];
        s1 += (v.x + v.y) + (v.z + v.w);
        s2 = fmaf(v.x, v.x, s2); s2 = fmaf(v.y, v.y, s2);
        s2 = fmaf(v.z, v.z, s2); s2 = fmaf(v.w, v.w, s2);
        mn = fminf(mn, fminf(fminf(v.x, v.y), fminf(v.z, v.w)));
    }
    s1 = wsum(s1); s2 = wsum(s2); mn = wmin(mn);
    if (lid == 0) { redA[wid] = s1; redB[wid] = s2; redC[wid] = mn; }
    __syncthreads();

    if (tid == 0) {
        float S1 = 0.f, S2 = 0.f, MN = INFINITY;
#pragma unroll
        for (int w = 0; w < NW; ++w) {
            S1 += redA[w]; S2 += redB[w]; MN = fminf(MN, redC[w]);
        }
        S1 *= 0.5f;            // rescale raw sums to z = 0.5*x domain
        S2 *= 0.25f;
        MN *= 0.5f;
        const float k = (float)D;
        float disc  = fmaxf(fmaf(S1, S1, -k * (S2 - 1.0f)), 0.f);
        float tau   = (S1 - sqrtf(disc)) / k;
        float sum_p = fmaf(k * tau, tau, fmaf(-2.f * S1, tau, S2));
        s_tau = tau;
        if (tau <= MN && sum_p > 0.f) {           // dense support: closed form valid
            s_logsum = __logf(sum_p);
            s_flag = 1.f;
        } else {
            s_flag = 0.f;
        }
    }
    __syncthreads();

    // ---- Fallback: exact reference bisection (block-uniform branch) ----
    if (s_flag == 0.f) {
        // recompute block max (only needed here)
        float mx = -INFINITY;
        for (int i = tid; i < D4; i += NT) {
            float4 v = x4[i];
            mx = fmaxf(mx, fmaxf(fmaxf(v.x, v.y), fmaxf(v.z, v.w)));
        }
        mx = wmax(mx);
        __syncthreads();
        if (lid == 0) redA[wid] = mx;
        __syncthreads();
        if (tid == 0) {
            float M = -INFINITY;
#pragma unroll
            for (int w = 0; w < NW; ++w) M = fmaxf(M, redA[w]);
            s_bc = 0.5f * M;
        }
        __syncthreads();
        float mxv    = s_bc;
        float tau_lo = mxv - 1.0f;
        float tau_hi = mxv - sqrtf(1.0f / (float)D);
        float f_lo   = block_relu2_sum(x4, tau_lo, redA, &s_bc) - 1.0f;
        float dm     = tau_hi - tau_lo;
        float tau_m  = tau_lo;
        for (int it = 0; it < 50; ++it) {
            dm *= 0.5f;
            tau_m = tau_lo + dm;
            float f_m = block_relu2_sum(x4, tau_m, redA, &s_bc) - 1.0f;
            if (f_m * f_lo >= 0.f) tau_lo = tau_m;  // uniform across block
        }
        float sp = block_relu2_sum(x4, tau_m, redA, &s_bc);
        if (tid == 0) {
            s_tau = tau_m;
            s_logsum = __logf(sp);
        }
        __syncthreads();
    }

    const float tau    = s_tau;
    const float logsum = s_logsum;

    // ---- Pass 2: re-read X (L2 hit), write log p with streaming stores ----
#pragma unroll 4
    for (int i = tid; i < D4; i += NT) {
        float4 v = __ldcs(&x4[i]);   // evict-first: row is dead after this read
        float4 r;
        float t;
        t = fmaf(0.5f, v.x, -tau); r.x = (t > 0.f) ? fmaf(2.f, __logf(t), -logsum) : -INFINITY;
        t = fmaf(0.5f, v.y, -tau); r.y = (t > 0.f) ? fmaf(2.f, __logf(t), -logsum) : -INFINITY;
        t = fmaf(0.5f, v.z, -tau); r.z = (t > 0.f) ? fmaf(2.f, __logf(t), -logsum) : -INFINITY;
        t = fmaf(0.5f, v.w, -tau); r.w = (t > 0.f) ? fmaf(2.f, __logf(t), -logsum) : -INFINITY;
        __stcs(&y4[i], r);           // streaming store: don't pollute L2
    }
}

extern "C" void kernel_launch(void* const* d_in, const int* in_sizes, int n_in,
                              void* d_out, int out_size) {
    const float* X = (const float*)d_in[0];
    float* Y = (float*)d_out;
    const int rows = in_sizes[0] / D;
    log_entmax_kernel<<<rows, NT>>>(X, Y);
}